// round 7
// baseline (speedup 1.0000x reference)
#include <cuda_runtime.h>
#include <cstring>

#define NLAYERS 200
#define KSIZE   7
#define L_IN    1388
#define NPAIR   694        // float2 pairs per row
#define FC_IN   188
#define FC_OUT  91
#define NT      128        // 4 warps, one ROW per CTA
#define C       6          // pairs per lane (32*6=192 per warp, 4*192=768 >= 694)
#define STG_N   768

// Packed dual-fp32 FMA (Blackwell f32x2).
static __device__ __forceinline__ float2 ffma2(float2 a, float2 b, float2 c) {
    unsigned long long ua, ub, uc, ud;
    memcpy(&ua, &a, 8); memcpy(&ub, &b, 8); memcpy(&uc, &c, 8);
    asm("fma.rn.f32x2 %0, %1, %2, %3;" : "=l"(ud) : "l"(ua), "l"(ub), "l"(uc));
    float2 d; memcpy(&d, &ud, 8);
    return d;
}

static __device__ __forceinline__ float2 shfl_down1_f2(float2 v) {
    float2 r;
    r.x = __shfl_down_sync(0xffffffffu, v.x, 1);
    r.y = __shfl_down_sync(0xffffffffu, v.y, 1);
    return r;
}

// Conv body at compile-time pair-chunk CC with halo pairs h[0..2].
template<int CC>
static __device__ __forceinline__ void conv_body(float2* p, const float2* w,
                                                 float2 b, bool relu, float2* h)
{
    float2 s0 = make_float2(p[0].y, p[1].x);
    float2 s1 = make_float2(p[1].y, p[2].x);
    float2 s2 = make_float2(p[2].y, p[3].x);
    #pragma unroll
    for (int j = 0; j < CC; j++) {
        float2 v1 = (j + 1 < CC) ? p[j + 1] : h[j + 1 - CC];
        float2 v2 = (j + 2 < CC) ? p[j + 2] : h[j + 2 - CC];
        float2 v3 = (j + 3 < CC) ? p[j + 3] : h[j + 3 - CC];
        float2 acc = b;
        acc = ffma2(w[0], p[j], acc);
        acc = ffma2(w[1], s0,   acc);
        acc = ffma2(w[2], v1,   acc);
        acc = ffma2(w[3], s1,   acc);
        acc = ffma2(w[4], v2,   acc);
        acc = ffma2(w[5], s2,   acc);
        acc = ffma2(w[6], v3,   acc);
        float2 snext = s2;
        if (j < CC - 1) {
            float2 v4 = (j + 4 < CC) ? p[j + 4] : h[j + 4 - CC];
            snext = make_float2(v3.y, v4.x);
        }
        if (relu) { acc.x = fmaxf(acc.x, 0.0f); acc.y = fmaxf(acc.y, 0.0f); }
        p[j] = acc;
        s0 = s1; s1 = s2; s2 = snext;
    }
}

// Cooperative phase with NW live warps (warp w owns pairs [w*192, w*192+192)).
// Halo: warp w lane 31 needs warp w+1's first 3 pairs -> smem, double-buffered
// by layer parity, one named barrier (id 1, NW*32 threads) per layer.
template<int NW>
static __device__ __forceinline__ void coop_phase(float2* p, int layer0, int nl,
                                                  const float2* __restrict__ ws2,
                                                  const float2* __restrict__ bs2,
                                                  float2 (*halo)[4][3],
                                                  int wid, int lane)
{
    #pragma unroll 1
    for (int i = 0; i < nl; i++) {
        const int L = layer0 + i;
        float2 (*buf)[3] = halo[L & 1];
        if (wid != 0 && lane == 0) {
            buf[wid][0] = p[0]; buf[wid][1] = p[1]; buf[wid][2] = p[2];
        }
        asm volatile("bar.sync 1, %0;" :: "r"(NW * 32) : "memory");

        float2 w[KSIZE];
        #pragma unroll
        for (int k = 0; k < KSIZE; k++) w[k] = ws2[L * KSIZE + k];
        float2 b = bs2[L];

        float2 h[3];
        #pragma unroll
        for (int j = 0; j < 3; j++) h[j] = shfl_down1_f2(p[j]);
        if (wid < NW - 1 && lane == 31) {
            h[0] = buf[wid + 1][0]; h[1] = buf[wid + 1][1]; h[2] = buf[wid + 1][2];
        }
        conv_body<C>(p, w, b, true, h);   // all coop layers < 199 -> ReLU
    }
}

// Solo phase (warp 0): halo purely via SHFL.
template<int CC>
static __device__ __forceinline__ void conv_phase(float2* p, int layer0, int nl,
                                                  const float2* __restrict__ ws2,
                                                  const float2* __restrict__ bs2)
{
    #pragma unroll 1
    for (int i = 0; i < nl; i++) {
        const int L = layer0 + i;
        float2 w[KSIZE];
        #pragma unroll
        for (int k = 0; k < KSIZE; k++) w[k] = ws2[L * KSIZE + k];
        float2 b = bs2[L];
        float2 h[3];
        #pragma unroll
        for (int j = 0; j < 3; j++) h[j] = shfl_down1_f2(p[j]);
        conv_body<CC>(p, w, b, (L != NLAYERS - 1), h);
    }
}

template<int CO, int CN, int VIN>
static __device__ __forceinline__ void repack(float2* p, float2* stg, int lane)
{
    __syncwarp();
    #pragma unroll
    for (int c = 0; c < CO; c++) {
        int g = lane * CO + c;
        if (g < VIN) stg[g] = p[c];
    }
    __syncwarp();
    #pragma unroll
    for (int c = 0; c < CN; c++) {
        int g = lane * CN + c;
        p[c] = (g < VIN) ? stg[g] : make_float2(0.0f, 0.0f);
    }
    __syncwarp();
}

__global__ __launch_bounds__(NT, 7)
void conv200_kernel(const float* __restrict__ x,
                    const float* __restrict__ conv_w,
                    const float* __restrict__ conv_b,
                    const float* __restrict__ fc_w,
                    const float* __restrict__ fc_b,
                    float* __restrict__ out)
{
    __shared__ float2 stage[STG_N];             // 6.1 KB
    __shared__ float2 ws2[NLAYERS * KSIZE];     // 11.2 KB packed (w,w)
    __shared__ float2 bs2[NLAYERS];             // 1.6 KB packed (b,b)
    __shared__ float2 halo_sm[2][4][3];         // double-buffered halos

    const int t    = threadIdx.x;
    const int wid  = t >> 5;
    const int lane = t & 31;

    for (int j = t; j < NLAYERS * KSIZE; j += NT) {
        float w = conv_w[j];
        ws2[j] = make_float2(w, w);
    }
    for (int j = t; j < NLAYERS; j += NT) {
        float b = conv_b[j];
        bs2[j] = make_float2(b, b);
    }

    const int row = blockIdx.x;                 // one CTA = one row, 4 warps
    const float2* xr = reinterpret_cast<const float2*>(x + (size_t)row * L_IN);

    for (int j = t; j < STG_N; j += NT)
        stage[j] = (j < NPAIR) ? __ldg(&xr[j]) : make_float2(0.0f, 0.0f);
    __syncthreads();

    // blocked registers: warp w, lane l owns pairs [w*192 + l*6, +6)
    float2 p[C];
    const int G0 = wid * (32 * C) + lane * C;
    #pragma unroll
    for (int c = 0; c < C; c++) p[c] = stage[G0 + c];

    // ---- cooperative phases: warps drop out as the valid region shrinks ----
    // V(i) = 694 - 3i pairs. Warp 3 useless once V<=576 (layer 40),
    // warp 2 once V<=384 (layer 104), warp 1 once V<=192 (layer 168).
    coop_phase<4>(p,   0, 40, ws2, bs2, halo_sm, wid, lane);
    if (wid < 3) coop_phase<3>(p,  40, 64, ws2, bs2, halo_sm, wid, lane);
    if (wid < 2) coop_phase<2>(p, 104, 64, ws2, bs2, halo_sm, wid, lane);

    if (wid == 0) {
        // ---- solo: layers 168..199 (V: 190 -> 94), shrink C for tail ----
        conv_phase<6>(p, 168, 10, ws2, bs2);            // V(178)=160
        repack<6, 5, 160>(p, stage, lane);
        conv_phase<5>(p, 178, 11, ws2, bs2);            // V(189)=127
        repack<5, 4, 127>(p, stage, lane);
        conv_phase<4>(p, 189, 11, ws2, bs2);            // V(200)=94 -> output

        // gather final 94 valid pairs (188 elements)
        __syncwarp();
        #pragma unroll
        for (int c = 0; c < 4; c++) {
            int g = lane * 4 + c;
            if (g < FC_IN / 2) stage[g] = p[c];
        }
        __syncwarp();

        // FC 188->91 + sigmoid: lane handles outputs {lane, lane+32, lane+64}
        const float2* fw2 = reinterpret_cast<const float2*>(fc_w);
        float2 acc[3];
        #pragma unroll
        for (int u = 0; u < 3; u++) acc[u] = make_float2(0.0f, 0.0f);
        int o0 = lane, o1 = lane + 32, o2 = lane + 64;
        int c2 = (o2 < FC_OUT) ? o2 : (FC_OUT - 1);
        const float2* r0w = fw2 + (size_t)o0 * (FC_IN / 2);
        const float2* r1w = fw2 + (size_t)o1 * (FC_IN / 2);
        const float2* r2w = fw2 + (size_t)c2 * (FC_IN / 2);
        #pragma unroll 2
        for (int j = 0; j < FC_IN / 2; j++) {
            float2 hv = stage[j];
            acc[0] = ffma2(__ldg(&r0w[j]), hv, acc[0]);
            acc[1] = ffma2(__ldg(&r1w[j]), hv, acc[1]);
            acc[2] = ffma2(__ldg(&r2w[j]), hv, acc[2]);
        }
        float* orow = out + (size_t)row * FC_OUT;
        float s0 = acc[0].x + acc[0].y + __ldg(&fc_b[o0]);
        float s1 = acc[1].x + acc[1].y + __ldg(&fc_b[o1]);
        orow[o0] = 1.0f / (1.0f + __expf(-s0));
        orow[o1] = 1.0f / (1.0f + __expf(-s1));
        if (o2 < FC_OUT) {
            float s2 = acc[2].x + acc[2].y + __ldg(&fc_b[o2]);
            orow[o2] = 1.0f / (1.0f + __expf(-s2));
        }
    }
}

extern "C" void kernel_launch(void* const* d_in, const int* in_sizes, int n_in,
                              void* d_out, int out_size)
{
    const float* x      = (const float*)d_in[0];   // [1024, 1388]
    const float* conv_w = (const float*)d_in[1];   // [200, 7]
    const float* conv_b = (const float*)d_in[2];   // [200]
    const float* fc_w   = (const float*)d_in[3];   // [91, 188]
    const float* fc_b   = (const float*)d_in[4];   // [91]
    float* out          = (float*)d_out;           // [1024, 91]

    const int B = in_sizes[0] / L_IN;              // 1024 rows
    conv200_kernel<<<B, NT>>>(x, conv_w, conv_b, fc_w, fc_b, out);
}

// round 8
// speedup vs baseline: 1.3224x; 1.3224x over previous
#include <cuda_runtime.h>
#include <cstring>

#define NLAYERS 200
#define KSIZE   7
#define L_IN    1388
#define FC_IN   188
#define FC_OUT  91
#define WPC     4
#define NT      (32 * WPC)

// Packed dual-fp32 FMA (Blackwell f32x2).
static __device__ __forceinline__ float2 ffma2(float2 a, float2 b, float2 c) {
    unsigned long long ua, ub, uc, ud;
    memcpy(&ua, &a, 8); memcpy(&ub, &b, 8); memcpy(&uc, &c, 8);
    asm("fma.rn.f32x2 %0, %1, %2, %3;" : "=l"(ud) : "l"(ua), "l"(ub), "l"(uc));
    float2 d; memcpy(&d, &ud, 8);
    return d;
}

// Far-pair layout: lane l owns packed positions g = l*C + c, c<C, where
// P[g] = (h[g], h[g+D]) and 32*C == D. Conv taps are ALL pair-aligned:
// P'[g] = sum_k w[k]*P[g+k]. Halo = next lane's first 6 pairs via rotated
// SHFL; lane 31 (seam) needs h[D+m] = P[m].y from lane 0 -> predicated swap.
// The wrong .y it gets only feeds the y-half tail, which is garbage that
// tracks the shrinking valid length (outputs beyond V are never consumed).
template<int C>
static __device__ __forceinline__ void phase(float2* p, int layer0, int nl,
                                             const float2* __restrict__ ws2,
                                             const float2* __restrict__ bs2,
                                             int lane)
{
    #pragma unroll 1
    for (int i = 0; i < nl; i++) {
        const int L = layer0 + i;
        float2 w[KSIZE];
        #pragma unroll
        for (int k = 0; k < KSIZE; k++) w[k] = ws2[L * KSIZE + k];
        const float2 b = bs2[L];

        float2 rot[6];
        #pragma unroll
        for (int m = 0; m < 6; m++) {
            float rx = __shfl_sync(0xffffffffu, p[m].x, lane + 1); // 31 wraps to 0
            float ry = __shfl_sync(0xffffffffu, p[m].y, lane + 1);
            rot[m] = make_float2((lane == 31) ? ry : rx, ry);
        }

        const bool relu = (L != NLAYERS - 1);
        #pragma unroll
        for (int j = 0; j < C; j++) {
            float2 acc = b;
            acc = ffma2(w[0], p[j], acc);
            #pragma unroll
            for (int k = 1; k < KSIZE; k++) {
                float2 v = (j + k < C) ? p[j + k] : rot[j + k - C];
                acc = ffma2(w[k], v, acc);
            }
            if (relu) { acc.x = fmaxf(acc.x, 0.0f); acc.y = fmaxf(acc.y, 0.0f); }
            p[j] = acc;   // ascending in-place: p[j] only read by outputs <= j
        }
    }
}

// Re-split from (DO, CO) to (DN, CN) through the per-warp float stage.
// VF = valid element count at the fold layer. Gathers h[0..VF) from x/y
// components, zero-fills to 2*DN, re-reads as new far-pairs.
template<int CO, int CN, int DO, int DN, int VF>
static __device__ __forceinline__ void fold(float2* p, float* stg, int lane)
{
    __syncwarp();
    for (int j = lane; j < 2 * DN; j += 32) stg[j] = 0.0f;
    __syncwarp();
    #pragma unroll
    for (int c = 0; c < CO; c++) {
        int g = lane * CO + c;
        stg[g] = p[c].x;                       // x half: h[0..DO), DO < VF
        if (DO + g < VF) stg[DO + g] = p[c].y; // y half: h[DO..VF)
    }
    __syncwarp();
    #pragma unroll
    for (int c = 0; c < CN; c++) {
        int g = lane * CN + c;
        p[c] = make_float2(stg[g], stg[g + DN]);
    }
    __syncwarp();
}

__global__ __launch_bounds__(NT, 2)
void conv200_kernel(const float* __restrict__ x,
                    const float* __restrict__ conv_w,
                    const float* __restrict__ conv_b,
                    const float* __restrict__ fc_w,
                    const float* __restrict__ fc_b,
                    float* __restrict__ out)
{
    __shared__ __align__(16) float stg_all[WPC][1024];   // 16 KB per-warp stages
    __shared__ float2 ws2[NLAYERS * KSIZE];              // 11.2 KB packed (w,w)
    __shared__ float2 bs2[NLAYERS];                      // 1.6 KB packed (b,b)

    const int t    = threadIdx.x;
    const int wid  = t >> 5;
    const int lane = t & 31;

    for (int j = t; j < NLAYERS * KSIZE; j += NT) {
        float w = conv_w[j];
        ws2[j] = make_float2(w, w);
    }
    for (int j = t; j < NLAYERS; j += NT) {
        float b = conv_b[j];
        bs2[j] = make_float2(b, b);
    }
    __syncthreads();   // only block-wide barrier

    const int row = blockIdx.x * WPC + wid;   // one warp = one row
    const float* xr = x + (size_t)row * L_IN;
    float* stg = stg_all[wid];

    // ---- initial far-pair pack: D=704, C=22 (two coalesced passes) ----
    float2 p[22];
    for (int j = lane; j < 1024; j += 32) stg[j] = __ldg(&xr[j]);
    __syncwarp();
    #pragma unroll
    for (int c = 0; c < 22; c++) {
        int g = lane * 22 + c;
        p[c].x = stg[g];
        p[c].y = (704 + g < 1024) ? stg[704 + g] : 0.0f;
    }
    __syncwarp();
    for (int j = lane; j < 384; j += 32) {
        int s = 1024 + j;
        stg[j] = (s < L_IN) ? __ldg(&xr[s]) : 0.0f;
    }
    __syncwarp();
    #pragma unroll
    for (int c = 0; c < 22; c++) {
        int g = lane * 22 + c;
        if (704 + g >= 1024) p[c].y = stg[704 + g - 1024];
    }

    // ---- 200 layers: 5 phases, 4 folds. V(i) = 1388 - 6i ----
    phase<22>(p,   0, 61, ws2, bs2, lane);            // D=704
    fold<22, 16, 704, 512, 1022>(p, stg, lane);
    phase<16>(p,  61, 43, ws2, bs2, lane);            // D=512
    fold<16, 12, 512, 384,  764>(p, stg, lane);
    phase<12>(p, 104, 42, ws2, bs2, lane);            // D=384
    fold<12,  8, 384, 256,  512>(p, stg, lane);
    phase< 8>(p, 146, 22, ws2, bs2, lane);            // D=256
    fold< 8,  6, 256, 192,  380>(p, stg, lane);
    phase< 6>(p, 168, 32, ws2, bs2, lane);            // D=192, final V=188<=192

    // ---- gather final 188 elements (all in x half) ----
    __syncwarp();
    #pragma unroll
    for (int c = 0; c < 6; c++) stg[lane * 6 + c] = p[c].x;   // fills [0,192)
    __syncwarp();

    // ---- FC 188->91 + sigmoid: lane handles outputs {lane, lane+32, lane+64} ----
    {
        const float2* hv2 = reinterpret_cast<const float2*>(stg);
        const float2* fw2 = reinterpret_cast<const float2*>(fc_w);
        float2 acc[3];
        #pragma unroll
        for (int u = 0; u < 3; u++) acc[u] = make_float2(0.0f, 0.0f);
        int o0 = lane, o1 = lane + 32, o2 = lane + 64;
        int c2 = (o2 < FC_OUT) ? o2 : (FC_OUT - 1);
        const float2* r0w = fw2 + (size_t)o0 * (FC_IN / 2);
        const float2* r1w = fw2 + (size_t)o1 * (FC_IN / 2);
        const float2* r2w = fw2 + (size_t)c2 * (FC_IN / 2);
        #pragma unroll 2
        for (int j = 0; j < FC_IN / 2; j++) {
            float2 hv = hv2[j];
            acc[0] = ffma2(__ldg(&r0w[j]), hv, acc[0]);
            acc[1] = ffma2(__ldg(&r1w[j]), hv, acc[1]);
            acc[2] = ffma2(__ldg(&r2w[j]), hv, acc[2]);
        }
        float* orow = out + (size_t)row * FC_OUT;
        float s0 = acc[0].x + acc[0].y + __ldg(&fc_b[o0]);
        float s1 = acc[1].x + acc[1].y + __ldg(&fc_b[o1]);
        orow[o0] = 1.0f / (1.0f + __expf(-s0));
        orow[o1] = 1.0f / (1.0f + __expf(-s1));
        if (o2 < FC_OUT) {
            float s2 = acc[2].x + acc[2].y + __ldg(&fc_b[o2]);
            orow[o2] = 1.0f / (1.0f + __expf(-s2));
        }
    }
}

extern "C" void kernel_launch(void* const* d_in, const int* in_sizes, int n_in,
                              void* d_out, int out_size)
{
    const float* x      = (const float*)d_in[0];   // [1024, 1388]
    const float* conv_w = (const float*)d_in[1];   // [200, 7]
    const float* conv_b = (const float*)d_in[2];   // [200]
    const float* fc_w   = (const float*)d_in[3];   // [91, 188]
    const float* fc_b   = (const float*)d_in[4];   // [91]
    float* out          = (float*)d_out;           // [1024, 91]

    const int B = in_sizes[0] / L_IN;              // 1024 rows
    conv200_kernel<<<B / WPC, NT>>>(x, conv_w, conv_b, fc_w, fc_b, out);
}